// round 7
// baseline (speedup 1.0000x reference)
#include <cuda_runtime.h>
#include <cstdint>

// Transducer KD loss prep — persistent cp.async, fine-grained (2KB) stages.
// logits/teacher (N=8,T=200,U=50,V=500) fp32; y (N,U) i32; x_lens,y_lens (N,) i32.
// Output (2, N, T, U, 3) fp32.
//
// Task = one (s, n, t, u) ROW (student OR teacher), 160000 tasks.
// Each warp: private 2-stage x 2KB smem ring, cp.async.cg double-buffered,
// grid-stride persistent. Small stages keep smem at 16KB/block and regs low,
// so high occupancy (40 warps/SM) coexists with deep async MLP.

#define TN 8
#define TT 200
#define TU 50
#define TV 500
#define ROWS (TN * TT * TU)              // 80000
#define TASKS (2 * ROWS)                 // 160000
#define T_EPS 1e-10f
#define NEG_BIG -1e30f

#define WARPS_PER_BLOCK 4
#define NBLOCKS (148 * 12)               // 1776 persistent blocks
#define TOTAL_WARPS (NBLOCKS * WARPS_PER_BLOCK)   // 7104
#define STAGE_FLOATS 512                 // 2048 B per stage (500 used)

struct Pos {
    const float* gbase;   // row base in gmem
    int q;                // flat task id (== output triple index)
    int yoff;             // n*TU + u
    int act;              // mask
};

__device__ __forceinline__ void cp16(uint32_t smem_addr, const float* gptr) {
    asm volatile("cp.async.cg.shared.global [%0], [%1], 16;\n"
                 :: "r"(smem_addr), "l"(gptr));
}

__global__ void __launch_bounds__(WARPS_PER_BLOCK * 32, 10)
transducer_kd_kernel(const float* __restrict__ logits,
                     const float* __restrict__ teacher,
                     const int*   __restrict__ y,
                     const int*   __restrict__ x_lens,
                     const int*   __restrict__ y_lens,
                     float*       __restrict__ out)
{
    // [warp][stage][512 floats] = 4*2*2048B = 16 KB
    __shared__ __align__(16) float buf[WARPS_PER_BLOCK][2][STAGE_FLOATS];

    const int w    = threadIdx.x >> 5;
    const int lane = threadIdx.x & 31;
    const int gw   = blockIdx.x * WARPS_PER_BLOCK + w;
    const bool tail = (lane < 29);       // 125 float4 per row

    auto decode = [&](int q) -> Pos {
        Pos z;
        z.q = q;
        const int s = (q >= ROWS);
        const int r = q - s * ROWS;
        const int n  = r / (TT * TU);
        const int tu = r - n * (TT * TU);
        const int t  = tu / TU;
        const int u  = tu - t * TU;
        z.yoff = n * TU + u;
        z.act  = (t < __ldg(x_lens + n)) && (u < __ldg(y_lens + n));
        z.gbase = (s ? teacher : logits) + (size_t)r * TV;
        return z;
    };

    auto issue = [&](const Pos& z, int st) {
        if (!z.act) return;
        uint32_t sb = (uint32_t)__cvta_generic_to_shared(&buf[w][st][0]);
        const float* g = z.gbase;
        cp16(sb + (lane      ) * 16, g + (lane      ) * 4);
        cp16(sb + (lane + 32 ) * 16, g + (lane + 32 ) * 4);
        cp16(sb + (lane + 64 ) * 16, g + (lane + 64 ) * 4);
        if (tail)
            cp16(sb + (lane + 96) * 16, g + (lane + 96) * 4);
    };

    auto compute = [&](const Pos& z, int st) {
        float* o = out + (size_t)z.q * 3;
        if (!z.act) {
            if (lane < 3) o[lane] = 0.0f;
            return;
        }
        const float*  rbuf = &buf[w][st][0];
        const float4* r4 = (const float4*)rbuf;

        float4 v0 = r4[lane];
        float4 v1 = r4[lane + 32];
        float4 v2 = r4[lane + 64];
        float4 v3 = make_float4(NEG_BIG, NEG_BIG, NEG_BIG, NEG_BIG);
        if (tail) v3 = r4[lane + 96];

        float a = (__expf(v0.x) + __expf(v0.y)) + (__expf(v0.z) + __expf(v0.w));
        a += (__expf(v1.x) + __expf(v1.y)) + (__expf(v1.z) + __expf(v1.w));
        a += (__expf(v2.x) + __expf(v2.y)) + (__expf(v2.z) + __expf(v2.w));
        a += (__expf(v3.x) + __expf(v3.y)) + (__expf(v3.z) + __expf(v3.w));

        #pragma unroll
        for (int off = 16; off > 0; off >>= 1)
            a += __shfl_xor_sync(0xFFFFFFFFu, a, off);

        if (lane == 0) {
            const int yi = __ldg(y + z.yoff);
            const float ly = rbuf[yi];
            const float lb = rbuf[0];
            const float inv   = 1.0f / a;
            const float py    = __expf(ly) * inv;
            const float blank = __expf(lb) * inv;
            const float rem   = 1.0f - py - blank;
            if (z.q < ROWS) {
                o[0] = logf(fminf(fmaxf(py,    T_EPS), 1.0f));
                o[1] = logf(fminf(fmaxf(blank, T_EPS), 1.0f));
                o[2] = logf(fminf(fmaxf(rem,   T_EPS), 1.0f));
            } else {
                o[0] = py;
                o[1] = blank;
                o[2] = (rem < 0.0f) ? T_EPS : rem;
            }
        }
    };

    if (gw >= TASKS) return;

    Pos cur = decode(gw);
    issue(cur, 0);
    asm volatile("cp.async.commit_group;\n" ::: "memory");

    int stage = 0;
    for (int q = gw; q < TASKS; q += TOTAL_WARPS) {
        const int qn = q + TOTAL_WARPS;
        Pos nxt;
        nxt.act = 0; nxt.q = 0; nxt.yoff = 0; nxt.gbase = logits;
        if (qn < TASKS) {
            nxt = decode(qn);
            issue(nxt, stage ^ 1);
        }
        asm volatile("cp.async.commit_group;\n" ::: "memory");
        asm volatile("cp.async.wait_group 1;\n" ::: "memory");
        __syncwarp();

        compute(cur, stage);
        cur = nxt;
        stage ^= 1;
    }
}

extern "C" void kernel_launch(void* const* d_in, const int* in_sizes, int n_in,
                              void* d_out, int out_size)
{
    const float* logits  = (const float*)d_in[0];
    const float* teacher = (const float*)d_in[1];
    const int*   y       = (const int*)d_in[2];
    const int*   x_lens  = (const int*)d_in[3];
    const int*   y_lens  = (const int*)d_in[4];
    float* out = (float*)d_out;

    transducer_kd_kernel<<<NBLOCKS, WARPS_PER_BLOCK * 32>>>(
        logits, teacher, y, x_lens, y_lens, out);
}

// round 8
// speedup vs baseline: 1.0543x; 1.0543x over previous
#include <cuda_runtime.h>
#include <cstdint>

// Transducer KD loss prep — persistent + L2 prefetch-ahead.
// logits/teacher (N=8,T=200,U=50,V=500) fp32; y (N,U) i32; x_lens,y_lens (N,) i32.
// Output (2, N, T, U, 3) fp32.
//
// Task = one (s,n,t,u) row, 160000 tasks. Persistent warps, grid-stride.
// Per iteration: front-batched 4x LDG.128.cs of current row (L2 hit thanks to
// last iteration's prefetch), then prefetch.global.L2 of next iteration's row
// (no register, no scoreboard -> free DRAM MLP). Rows are 2000B (not line
// aligned) -> 17 x 128B prefetches cover any alignment.

#define TN 8
#define TT 200
#define TU 50
#define TV 500
#define ROWS (TN * TT * TU)              // 80000
#define TASKS (2 * ROWS)                 // 160000
#define T_EPS 1e-10f
#define NEG_BIG -1e30f

#define THREADS 256
#define WARPS_PER_BLOCK (THREADS / 32)
#define NBLOCKS (148 * 8)                // 1184 persistent blocks
#define TOTAL_WARPS (NBLOCKS * WARPS_PER_BLOCK)   // 9472

struct Task {
    const float* g;     // row base
    int q;              // flat task id (== output triple base / 3)
    int yoff;           // n*TU + u
    int act;
};

__device__ __forceinline__ void l2_prefetch(const void* p) {
    asm volatile("prefetch.global.L2 [%0];" :: "l"(p));
}

__global__ void __launch_bounds__(THREADS)
transducer_kd_kernel(const float* __restrict__ logits,
                     const float* __restrict__ teacher,
                     const int*   __restrict__ y,
                     const int*   __restrict__ x_lens,
                     const int*   __restrict__ y_lens,
                     float*       __restrict__ out)
{
    const int lane = threadIdx.x & 31;
    const int gw   = blockIdx.x * WARPS_PER_BLOCK + (threadIdx.x >> 5);
    const bool tail = (lane < 29);       // 125 float4 per row

    auto decode = [&](int q) -> Task {
        Task z;
        z.q = q;
        const int s = (q >= ROWS);
        const int r = q - s * ROWS;
        const int n  = r / (TT * TU);
        const int tu = r - n * (TT * TU);
        const int t  = tu / TU;
        const int u  = tu - t * TU;
        z.yoff = n * TU + u;
        z.act  = (t < __ldg(x_lens + n)) && (u < __ldg(y_lens + n));
        z.g    = (s ? teacher : logits) + (size_t)r * TV;
        return z;
    };

    if (gw >= TASKS) return;

    Task cur = decode(gw);
    // Prologue prefetch of the first row (partially useful).
    if (cur.act && lane < 17) l2_prefetch((const char*)cur.g + lane * 128);

    for (int q = gw; q < TASKS; q += TOTAL_WARPS) {
        // ---- front-batched loads of current row (hits L2 if prefetched) ----
        const float4* r4 = (const float4*)cur.g;
        float4 v0, v1, v2, v3;
        if (cur.act) {
            v0 = __ldcs(r4 + lane);
            v1 = __ldcs(r4 + lane + 32);
            v2 = __ldcs(r4 + lane + 64);
            v3 = make_float4(NEG_BIG, NEG_BIG, NEG_BIG, NEG_BIG);
            if (tail) v3 = __ldcs(r4 + lane + 96);
        }

        // ---- decode + prefetch next iteration's row ----
        const int qn = q + TOTAL_WARPS;
        Task nxt;
        nxt.act = 0; nxt.q = 0; nxt.yoff = 0; nxt.g = logits;
        if (qn < TASKS) {
            nxt = decode(qn);
            if (nxt.act && lane < 17)
                l2_prefetch((const char*)nxt.g + lane * 128);
        }

        // ---- compute current ----
        float* o = out + (size_t)cur.q * 3;
        if (!cur.act) {
            if (lane < 3) o[lane] = 0.0f;
        } else {
            float a = (__expf(v0.x) + __expf(v0.y)) + (__expf(v0.z) + __expf(v0.w));
            a += (__expf(v1.x) + __expf(v1.y)) + (__expf(v1.z) + __expf(v1.w));
            a += (__expf(v2.x) + __expf(v2.y)) + (__expf(v2.z) + __expf(v2.w));
            a += (__expf(v3.x) + __expf(v3.y)) + (__expf(v3.z) + __expf(v3.w));

            #pragma unroll
            for (int off = 16; off > 0; off >>= 1)
                a += __shfl_xor_sync(0xFFFFFFFFu, a, off);

            if (lane == 0) {
                const int yi = __ldg(y + cur.yoff);
                const float ly = __ldg(cur.g + yi);   // L2 hit (row just streamed)
                const float lb = __ldg(cur.g);
                const float inv   = 1.0f / a;
                const float py    = __expf(ly) * inv;
                const float blank = __expf(lb) * inv;
                const float rem   = 1.0f - py - blank;
                if (cur.q < ROWS) {
                    o[0] = logf(fminf(fmaxf(py,    T_EPS), 1.0f));
                    o[1] = logf(fminf(fmaxf(blank, T_EPS), 1.0f));
                    o[2] = logf(fminf(fmaxf(rem,   T_EPS), 1.0f));
                } else {
                    o[0] = py;
                    o[1] = blank;
                    o[2] = (rem < 0.0f) ? T_EPS : rem;
                }
            }
        }
        cur = nxt;
    }
}

extern "C" void kernel_launch(void* const* d_in, const int* in_sizes, int n_in,
                              void* d_out, int out_size)
{
    const float* logits  = (const float*)d_in[0];
    const float* teacher = (const float*)d_in[1];
    const int*   y       = (const int*)d_in[2];
    const int*   x_lens  = (const int*)d_in[3];
    const int*   y_lens  = (const int*)d_in[4];
    float* out = (float*)d_out;

    transducer_kd_kernel<<<NBLOCKS, THREADS>>>(
        logits, teacher, y, x_lens, y_lens, out);
}

// round 9
// speedup vs baseline: 1.1795x; 1.1188x over previous
#include <cuda_runtime.h>
#include <cstdint>

// Transducer KD loss prep.
// logits/teacher (N=8,T=200,U=50,V=500) fp32; y (N,U) i32; x_lens,y_lens (N,) i32.
// Output (2, N, T, U, 3) fp32.
//
// One warp per (n,t,u) position, both student+teacher rows (shared mask/y).
// The 8 row loads are emitted as asm-volatile LDG.128.cs so ptxas CANNOT
// re-interleave them with the exp chain (guaranteed MLP_p1 = 8, regardless
// of its register heuristics — the R4 regression). 128-thread blocks for
// finer scheduling granularity; gather logits re-fetched from L2 by lane 0.

#define TN 8
#define TT 200
#define TU 50
#define TV 500
#define ROWS (TN * TT * TU)     // 80000
#define T_EPS 1e-10f
#define NEG_BIG -1e30f

__device__ __forceinline__ float4 ldcs128(const float4* p) {
    float4 v;
    asm volatile("ld.global.cs.v4.f32 {%0,%1,%2,%3}, [%4];"
                 : "=f"(v.x), "=f"(v.y), "=f"(v.z), "=f"(v.w)
                 : "l"(p));
    return v;
}

__global__ void __launch_bounds__(128)
transducer_kd_kernel(const float* __restrict__ logits,
                     const float* __restrict__ teacher,
                     const int*   __restrict__ y,
                     const int*   __restrict__ x_lens,
                     const int*   __restrict__ y_lens,
                     float*       __restrict__ out)
{
    const int warp_global = (int)((blockIdx.x * blockDim.x + threadIdx.x) >> 5);
    const int lane = threadIdx.x & 31;
    if (warp_global >= ROWS) return;

    const int r  = warp_global;
    const int n  = r / (TT * TU);
    const int tu = r - n * (TT * TU);
    const int t  = tu / TU;
    const int u  = tu - t * TU;

    float* os = out + (size_t)r * 3;                 // student triple
    float* ot = out + (size_t)(ROWS + r) * 3;        // teacher triple

    const bool active = (t < x_lens[n]) && (u < y_lens[n]);
    if (!active) {
        if (lane < 3) { os[lane] = 0.0f; ot[lane] = 0.0f; }
        return;
    }

    const float* sbase = logits  + (size_t)r * TV;
    const float* tbase = teacher + (size_t)r * TV;
    const float4* s4 = (const float4*)sbase;
    const float4* t4 = (const float4*)tbase;
    const bool tail = (lane < 29);                   // 125 float4 per row

    // ---- Phase 1: 8 front-batched streaming loads (ordering enforced) ----
    float4 sv0 = ldcs128(s4 + lane);
    float4 sv1 = ldcs128(s4 + lane + 32);
    float4 sv2 = ldcs128(s4 + lane + 64);
    float4 tv0 = ldcs128(t4 + lane);
    float4 tv1 = ldcs128(t4 + lane + 32);
    float4 tv2 = ldcs128(t4 + lane + 64);
    float4 sv3 = make_float4(NEG_BIG, NEG_BIG, NEG_BIG, NEG_BIG);
    float4 tv3 = make_float4(NEG_BIG, NEG_BIG, NEG_BIG, NEG_BIG);
    if (tail) {
        sv3 = ldcs128(s4 + lane + 96);
        tv3 = ldcs128(t4 + lane + 96);
    }

    // ---- Phase 2: exp + tree sums (both rows) ----
    float sa = (__expf(sv0.x) + __expf(sv0.y)) + (__expf(sv0.z) + __expf(sv0.w));
    sa += (__expf(sv1.x) + __expf(sv1.y)) + (__expf(sv1.z) + __expf(sv1.w));
    sa += (__expf(sv2.x) + __expf(sv2.y)) + (__expf(sv2.z) + __expf(sv2.w));
    sa += (__expf(sv3.x) + __expf(sv3.y)) + (__expf(sv3.z) + __expf(sv3.w));
    float ta = (__expf(tv0.x) + __expf(tv0.y)) + (__expf(tv0.z) + __expf(tv0.w));
    ta += (__expf(tv1.x) + __expf(tv1.y)) + (__expf(tv1.z) + __expf(tv1.w));
    ta += (__expf(tv2.x) + __expf(tv2.y)) + (__expf(tv2.z) + __expf(tv2.w));
    ta += (__expf(tv3.x) + __expf(tv3.y)) + (__expf(tv3.z) + __expf(tv3.w));

    #pragma unroll
    for (int off = 16; off > 0; off >>= 1) {
        sa += __shfl_xor_sync(0xFFFFFFFFu, sa, off);
        ta += __shfl_xor_sync(0xFFFFFFFFu, ta, off);
    }

    if (lane == 0) {
        const int yi = __ldg(y + n * TU + u);
        // gathered logits: L2 hits (rows just streamed through L2)
        const float s_ly = __ldg(sbase + yi);
        const float t_ly = __ldg(tbase + yi);
        const float s_lb = __ldg(sbase);
        const float t_lb = __ldg(tbase);

        // student: log(clip(x, EPS, 1))
        const float sinv   = 1.0f / sa;
        const float spy    = __expf(s_ly) * sinv;
        const float sblank = __expf(s_lb) * sinv;
        const float srem   = 1.0f - spy - sblank;
        os[0] = logf(fminf(fmaxf(spy,    T_EPS), 1.0f));
        os[1] = logf(fminf(fmaxf(sblank, T_EPS), 1.0f));
        os[2] = logf(fminf(fmaxf(srem,   T_EPS), 1.0f));
        // teacher: raw probs; rem clamped to EPS if negative
        const float tinv   = 1.0f / ta;
        const float tpy    = __expf(t_ly) * tinv;
        const float tblank = __expf(t_lb) * tinv;
        const float trem   = 1.0f - tpy - tblank;
        ot[0] = tpy;
        ot[1] = tblank;
        ot[2] = (trem < 0.0f) ? T_EPS : trem;
    }
}

extern "C" void kernel_launch(void* const* d_in, const int* in_sizes, int n_in,
                              void* d_out, int out_size)
{
    const float* logits  = (const float*)d_in[0];
    const float* teacher = (const float*)d_in[1];
    const int*   y       = (const int*)d_in[2];
    const int*   x_lens  = (const int*)d_in[3];
    const int*   y_lens  = (const int*)d_in[4];
    float* out = (float*)d_out;

    const int WARPS_PER_BLOCK = 4;          // 128 threads
    const int blocks = (ROWS + WARPS_PER_BLOCK - 1) / WARPS_PER_BLOCK;
    transducer_kd_kernel<<<blocks, WARPS_PER_BLOCK * 32>>>(
        logits, teacher, y, x_lens, y_lens, out);
}